// round 15
// baseline (speedup 1.0000x reference)
#include <cuda_runtime.h>
#include <stdint.h>

// Problem constants: x [N, C, H, W] fp32
#define N_S   16
#define C_CH  128
#define HW    16384           // 128*128
#define HW4   4096            // HW / 4
#define K_TOP 1638            // max(int(0.1 * 16384), 1)

__device__ float d_stats[N_S * HW];   // per-(n, p) channel-sum
__device__ float d_scale[N_S * HW];   // per-(n, p) fused blend factor

// ---------------------------------------------------------------------------
// Kernel A: channel-sum per spatial column, 2 threads per column (parity
// split; bit-identical to the 98.8us kernel: parity 0 sums even channels
// sequentially == s0, parity 1 odds == s1, combined s0 + s1).
// __launch_bounds__(128, 8) caps regs at 64: enough for the 8-deep float4
// load batch to stay register-resident (MLP~8) WITHOUT the 255-reg collapse
// that killed occupancy in R14. Block=128 -> grid=1024 for wave balance.
// ---------------------------------------------------------------------------
__global__ void __launch_bounds__(128, 8) stats_kernel(const float* __restrict__ x) {
    const int tid    = threadIdx.x;
    const int colloc = tid & 63;                     // column within block
    const int parity = tid >> 6;                     // 0: evens, 1: odds
    const int col    = blockIdx.x * 64 + colloc;     // [0, N_S*HW4)
    const int n      = col >> 12;
    const int p4     = col & (HW4 - 1);

    const float4* xp = reinterpret_cast<const float4*>(x)
                     + ((size_t)n << 19) + ((size_t)parity << 12) + p4;

    float4 s = make_float4(0.f, 0.f, 0.f, 0.f);
    #pragma unroll
    for (int k0 = 0; k0 < 64; k0 += 8) {
        float4 v[8];
        #pragma unroll
        for (int i = 0; i < 8; ++i)
            v[i] = __ldcs(xp + ((size_t)(k0 + i) << 13));   // stride 2 channels
        #pragma unroll
        for (int i = 0; i < 8; ++i) {                        // sequential order
            s.x += v[i].x; s.y += v[i].y; s.z += v[i].z; s.w += v[i].w;
        }
    }

    __shared__ float4 sm[64];
    if (parity == 1) sm[colloc] = s;
    __syncthreads();
    if (parity == 0) {
        float4 s1 = sm[colloc];
        float4 t;                                            // s0 + s1, exact order
        t.x = s.x + s1.x; t.y = s.y + s1.y; t.z = s.z + s1.z; t.w = s.w + s1.w;
        __stcg(reinterpret_cast<float4*>(d_stats) + col, t);
    }
}

// ---------------------------------------------------------------------------
// Kernel B: exact per-sample top-k via MSB-first radix select (register-
// resident keys, warp-aggregated histogram). Stable lowest-index tie-break.
// Writes fused blend factor  mask*tau + (1-tau). One block/sample.
// ---------------------------------------------------------------------------
__device__ __forceinline__ unsigned f2key(float f) {
    unsigned u = __float_as_uint(f);
    return u ^ ((unsigned)((int)u >> 31) | 0x80000000u);   // order-preserving
}

__device__ __forceinline__ unsigned block_reduce_add(unsigned v, unsigned* red) {
    #pragma unroll
    for (int o = 16; o; o >>= 1) v += __shfl_down_sync(0xFFFFFFFFu, v, o);
    int lane = threadIdx.x & 31, wid = threadIdx.x >> 5;
    if (lane == 0) red[wid] = v;
    __syncthreads();
    if (wid == 0) {
        unsigned r = red[lane];
        #pragma unroll
        for (int o = 16; o; o >>= 1) r += __shfl_down_sync(0xFFFFFFFFu, r, o);
        if (lane == 0) red[0] = r;
    }
    __syncthreads();
    unsigned r = red[0];
    __syncthreads();
    return r;
}

__global__ void __launch_bounds__(1024) select_kernel(const float* __restrict__ tau_p) {
    const int n   = blockIdx.x;
    const int tid = threadIdx.x;
    const float* st = d_stats + n * HW;

    unsigned key[16];
    #pragma unroll
    for (int i = 0; i < 16; ++i)
        key[i] = f2key(__ldcg(st + i * 1024 + tid));   // coalesced, L2

    __shared__ unsigned hist[256];
    __shared__ unsigned red[32];
    __shared__ unsigned s_prefix, s_rem;
    if (tid == 0) { s_prefix = 0u; s_rem = K_TOP; }
    __syncthreads();

    for (int shift = 24; shift >= 0; shift -= 8) {
        if (tid < 256) hist[tid] = 0u;
        __syncthreads();
        unsigned prefix = s_prefix;
        unsigned himask = (shift == 24) ? 0u : (0xFFFFFFFFu << (shift + 8));

        #pragma unroll
        for (int i = 0; i < 16; ++i) {
            unsigned u = key[i];
            bool act = ((u & himask) == prefix);
            unsigned bucket = act ? ((u >> shift) & 255u) : 0xFFFFFFFFu;
            unsigned m = __match_any_sync(0xFFFFFFFFu, bucket);
            if (act && ((threadIdx.x & 31) == (unsigned)(__ffs(m) - 1)))
                atomicAdd(&hist[bucket], (unsigned)__popc(m));
        }
        __syncthreads();
        if (tid == 0) {
            unsigned rem = s_rem;
            int b = 255;
            for (; b > 0; --b) {
                if (hist[b] >= rem) break;
                rem -= hist[b];
            }
            s_prefix = prefix | ((unsigned)b << shift);
            s_rem    = rem;
        }
        __syncthreads();
    }

    const unsigned T = s_prefix;   // k-th largest key
    const unsigned r = s_rem;      // #ties kept (lowest index first)

    unsigned myT = 0;
    #pragma unroll
    for (int i = 0; i < 16; ++i) myT += (key[i] == T) ? 1u : 0u;
    unsigned cntT = block_reduce_add(myT, red);

    int M = HW - 1;
    if (cntT != r) {               // rare: more ties than slots
        int lo = 0, hi = HW - 1;
        while (lo < hi) {
            int mid = (lo + hi) >> 1;
            unsigned c = 0;
            #pragma unroll
            for (int i = 0; i < 16; ++i) {
                int p = i * 1024 + tid;
                c += (key[i] == T && p <= mid) ? 1u : 0u;
            }
            c = block_reduce_add(c, red);
            if (c >= r) hi = mid; else lo = mid + 1;
        }
        M = lo;
    }

    const float tau  = *tau_p;
    const float base = 1.0f - tau;
    #pragma unroll
    for (int i = 0; i < 16; ++i) {
        int p = i * 1024 + tid;
        unsigned u = key[i];
        float m = (u > T || (u == T && p <= M)) ? 1.0f : 0.0f;
        d_scale[n * HW + p] = m * tau + base;
    }
}

// ---------------------------------------------------------------------------
// Kernel C: out = x * scale[n][p]. Each thread owns ONE spatial column and
// streams 32 channels: scale float4 loaded ONCE into registers; x streamed
// with 8-deep register-resident load batches. __launch_bounds__(256, 4)
// caps regs at 64 (batch survives, occupancy stays 32 warps/SM).
// ---------------------------------------------------------------------------
__global__ void __launch_bounds__(256, 4) apply_kernel(const float* __restrict__ x,
                                                       float* __restrict__ out) {
    const int t  = blockIdx.x * 256 + threadIdx.x;   // [0, 262144)
    const int p4 = t & (HW4 - 1);
    const int n  = (t >> 12) & 15;
    const int cq = t >> 16;                          // channel quarter: 0..3

    const float4 s = __ldcg(reinterpret_cast<const float4*>(d_scale) + (n << 12) + p4);

    const size_t base = ((size_t)((n << 7) + (cq << 5)) << 12) + p4;
    const float4* xv = reinterpret_cast<const float4*>(x) + base;
    float4*       ov = reinterpret_cast<float4*>(out) + base;

    #pragma unroll
    for (int k0 = 0; k0 < 32; k0 += 8) {
        float4 v[8];
        #pragma unroll
        for (int i = 0; i < 8; ++i)
            v[i] = __ldcs(xv + ((size_t)(k0 + i) << 12));
        #pragma unroll
        for (int i = 0; i < 8; ++i) {
            float4 o;
            o.x = v[i].x * s.x; o.y = v[i].y * s.y;
            o.z = v[i].z * s.z; o.w = v[i].w * s.w;
            __stcs(ov + ((size_t)(k0 + i) << 12), o);
        }
    }
}

// ---------------------------------------------------------------------------
extern "C" void kernel_launch(void* const* d_in, const int* in_sizes, int n_in,
                              void* d_out, int out_size) {
    const float* x   = (const float*)d_in[0];
    const float* tau = (const float*)d_in[1];
    float*       out = (float*)d_out;

    stats_kernel <<<(N_S * HW4 * 2) / 128, 128>>>(x);       // 1024 blocks
    select_kernel<<<N_S, 1024>>>(tau);
    apply_kernel <<<(N_S * HW4 * 4) / 256, 256>>>(x, out);  // 1024 blocks
}

// round 16
// speedup vs baseline: 1.4921x; 1.4921x over previous
#include <cuda_runtime.h>
#include <stdint.h>

// Problem constants: x [N, C, H, W] fp32
#define N_S   16
#define C_CH  128
#define HW    16384           // 128*128
#define HW4   4096            // HW / 4
#define K_TOP 1638            // max(int(0.1 * 16384), 1)

__device__ float d_stats[N_S * HW];   // per-(n, p) channel-sum
__device__ float d_scale[N_S * HW];   // per-(n, p) fused blend factor

// ---------------------------------------------------------------------------
// Kernel A: channel-sum per spatial column, 2 threads per column (parity
// split; bit-identical accumulation order: parity 0 sums even channels
// sequentially == s0, parity 1 odds == s1, combined s0 + s1).
// __launch_bounds__(128, 8): regs capped at 64 so the 8-deep float4 batch is
// register-resident (MLP~8) at ~43% occupancy (proven 24.1us config).
// Loads use __ldcg (NOT .cs): deliberately retain x in L2 so apply can hit.
// ---------------------------------------------------------------------------
__global__ void __launch_bounds__(128, 8) stats_kernel(const float* __restrict__ x) {
    const int tid    = threadIdx.x;
    const int colloc = tid & 63;                     // column within block
    const int parity = tid >> 6;                     // 0: evens, 1: odds
    const int col    = blockIdx.x * 64 + colloc;     // [0, N_S*HW4)
    const int n      = col >> 12;
    const int p4     = col & (HW4 - 1);

    const float4* xp = reinterpret_cast<const float4*>(x)
                     + ((size_t)n << 19) + ((size_t)parity << 12) + p4;

    float4 s = make_float4(0.f, 0.f, 0.f, 0.f);
    #pragma unroll
    for (int k0 = 0; k0 < 64; k0 += 8) {
        float4 v[8];
        #pragma unroll
        for (int i = 0; i < 8; ++i)
            v[i] = __ldcg(xp + ((size_t)(k0 + i) << 13));   // stride 2 channels
        #pragma unroll
        for (int i = 0; i < 8; ++i) {                        // sequential order
            s.x += v[i].x; s.y += v[i].y; s.z += v[i].z; s.w += v[i].w;
        }
    }

    __shared__ float4 sm[64];
    if (parity == 1) sm[colloc] = s;
    __syncthreads();
    if (parity == 0) {
        float4 s1 = sm[colloc];
        float4 t;                                            // s0 + s1, exact order
        t.x = s.x + s1.x; t.y = s.y + s1.y; t.z = s.z + s1.z; t.w = s.w + s1.w;
        __stcg(reinterpret_cast<float4*>(d_stats) + col, t);
    }
}

// ---------------------------------------------------------------------------
// Kernel B: exact per-sample top-k via MSB-first radix select (register-
// resident keys, warp-aggregated histogram). Stable lowest-index tie-break.
// Bucket selection per round is now a BRANCHLESS suffix scan (no dependent
// break chain -> LDS issue-bound instead of latency-bound).
// ---------------------------------------------------------------------------
__device__ __forceinline__ unsigned f2key(float f) {
    unsigned u = __float_as_uint(f);
    return u ^ ((unsigned)((int)u >> 31) | 0x80000000u);   // order-preserving
}

__device__ __forceinline__ unsigned block_reduce_add(unsigned v, unsigned* red) {
    #pragma unroll
    for (int o = 16; o; o >>= 1) v += __shfl_down_sync(0xFFFFFFFFu, v, o);
    int lane = threadIdx.x & 31, wid = threadIdx.x >> 5;
    if (lane == 0) red[wid] = v;
    __syncthreads();
    if (wid == 0) {
        unsigned r = red[lane];
        #pragma unroll
        for (int o = 16; o; o >>= 1) r += __shfl_down_sync(0xFFFFFFFFu, r, o);
        if (lane == 0) red[0] = r;
    }
    __syncthreads();
    unsigned r = red[0];
    __syncthreads();
    return r;
}

__global__ void __launch_bounds__(1024) select_kernel(const float* __restrict__ tau_p) {
    const int n   = blockIdx.x;
    const int tid = threadIdx.x;
    const float* st = d_stats + n * HW;

    unsigned key[16];
    #pragma unroll
    for (int i = 0; i < 16; ++i)
        key[i] = f2key(__ldcg(st + i * 1024 + tid));   // coalesced, L2

    __shared__ unsigned hist[256];
    __shared__ unsigned red[32];
    __shared__ unsigned s_prefix, s_rem;
    if (tid == 0) { s_prefix = 0u; s_rem = K_TOP; }
    __syncthreads();

    for (int shift = 24; shift >= 0; shift -= 8) {
        if (tid < 256) hist[tid] = 0u;
        __syncthreads();
        unsigned prefix = s_prefix;
        unsigned himask = (shift == 24) ? 0u : (0xFFFFFFFFu << (shift + 8));

        #pragma unroll
        for (int i = 0; i < 16; ++i) {
            unsigned u = key[i];
            bool act = ((u & himask) == prefix);
            unsigned bucket = act ? ((u >> shift) & 255u) : 0xFFFFFFFFu;
            unsigned m = __match_any_sync(0xFFFFFFFFu, bucket);
            if (act && ((threadIdx.x & 31) == (unsigned)(__ffs(m) - 1)))
                atomicAdd(&hist[bucket], (unsigned)__popc(m));
        }
        __syncthreads();
        if (tid == 0) {
            // Branchless top-down suffix scan: exactly one bucket satisfies
            // run < rem <= run + hist[b]  (run = count strictly above b).
            const unsigned rem = s_rem;
            unsigned run = 0;
            int bsel = 0; unsigned rsel = rem;
            #pragma unroll 32
            for (int i = 255; i >= 0; --i) {
                unsigned h = hist[i];
                bool take = (run < rem) && (run + h >= rem);
                if (take) { bsel = i; rsel = rem - run; }
                run += h;
            }
            s_prefix = prefix | ((unsigned)bsel << shift);
            s_rem    = rsel;
        }
        __syncthreads();
    }

    const unsigned T = s_prefix;   // k-th largest key
    const unsigned r = s_rem;      // #ties kept (lowest index first)

    unsigned myT = 0;
    #pragma unroll
    for (int i = 0; i < 16; ++i) myT += (key[i] == T) ? 1u : 0u;
    unsigned cntT = block_reduce_add(myT, red);

    int M = HW - 1;
    if (cntT != r) {               // rare: more ties than slots
        int lo = 0, hi = HW - 1;
        while (lo < hi) {
            int mid = (lo + hi) >> 1;
            unsigned c = 0;
            #pragma unroll
            for (int i = 0; i < 16; ++i) {
                int p = i * 1024 + tid;
                c += (key[i] == T && p <= mid) ? 1u : 0u;
            }
            c = block_reduce_add(c, red);
            if (c >= r) hi = mid; else lo = mid + 1;
        }
        M = lo;
    }

    const float tau  = *tau_p;
    const float base = 1.0f - tau;
    #pragma unroll
    for (int i = 0; i < 16; ++i) {
        int p = i * 1024 + tid;
        unsigned u = key[i];
        float m = (u > T || (u == T && p <= M)) ? 1.0f : 0.0f;
        d_scale[n * HW + p] = m * tau + base;
    }
}

// ---------------------------------------------------------------------------
// Kernel C: out = x * scale[n][p]. Column-owning (scale float4 loaded once
// into registers, 32 channels streamed). Default launch bounds — the proven
// R11 configuration. Channel traversal REVERSED (high channels first, both
// across blocks via cq remap and within the k-loop): stats left x L2-resident
// most-recent = highest channels, so descending consumption is LRU-friendly.
// x reads .cs (last use), out stores .cs (don't pin L2).
// ---------------------------------------------------------------------------
__global__ void __launch_bounds__(256) apply_kernel(const float* __restrict__ x,
                                                    float* __restrict__ out) {
    const int t  = blockIdx.x * 256 + threadIdx.x;   // [0, 262144)
    const int p4 = t & (HW4 - 1);
    const int n  = (t >> 12) & 15;
    const int cq = 3 - (t >> 16);                    // reversed quarter: early blocks -> high channels

    const float4 s = __ldcg(reinterpret_cast<const float4*>(d_scale) + (n << 12) + p4);

    const size_t base = ((size_t)((n << 7) + (cq << 5)) << 12) + p4;
    const float4* xv = reinterpret_cast<const float4*>(x) + base;
    float4*       ov = reinterpret_cast<float4*>(out) + base;

    #pragma unroll
    for (int k0 = 24; k0 >= 0; k0 -= 8) {            // descending channel batches
        float4 v[8];
        #pragma unroll
        for (int i = 0; i < 8; ++i)
            v[i] = __ldcs(xv + ((size_t)(k0 + i) << 12));
        #pragma unroll
        for (int i = 0; i < 8; ++i) {
            float4 o;
            o.x = v[i].x * s.x; o.y = v[i].y * s.y;
            o.z = v[i].z * s.z; o.w = v[i].w * s.w;
            __stcs(ov + ((size_t)(k0 + i) << 12), o);
        }
    }
}

// ---------------------------------------------------------------------------
extern "C" void kernel_launch(void* const* d_in, const int* in_sizes, int n_in,
                              void* d_out, int out_size) {
    const float* x   = (const float*)d_in[0];
    const float* tau = (const float*)d_in[1];
    float*       out = (float*)d_out;

    stats_kernel <<<(N_S * HW4 * 2) / 128, 128>>>(x);       // 1024 blocks
    select_kernel<<<N_S, 1024>>>(tau);
    apply_kernel <<<(N_S * HW4 * 4) / 256, 256>>>(x, out);  // 1024 blocks
}